// round 1
// baseline (speedup 1.0000x reference)
#include <cuda_runtime.h>

#define Bb 16
#define Hh 256
#define Ww 256
#define Cc 64
#define M1m 20
#define M2m 20

// Scratch (device globals; no allocation allowed)
__device__ float2 g_A [Bb*Hh*M2m*Cc];   // forward w-transform   [b][h][ky][c]
__device__ float2 g_M [Bb*M2m*M1m*Cc];  // forward modes         [b][ky][kx][c]
__device__ float2 g_Mo[Bb*M2m*M1m*Cc];  // mixed modes (scaled)  [b][ky][kx][c]
__device__ float2 g_T [Bb*Hh*M2m*Cc];   // inverse h-expand      [b][h][ky][c]

#define TWO_PI_OVER_256 0.0245436926061702596f

// ---------------------------------------------------------------------------
// K1: A[b,h,ky,c] = sum_w P[b,h,w,c] * e^{-2*pi*i*ky*w/W}
// block = (h, b); 320 threads = 20 ky * 16 c-groups of 4
// ---------------------------------------------------------------------------
__global__ void __launch_bounds__(320) k_fwd_w(const float* __restrict__ pts) {
    extern __shared__ float sm[];
    float* sP = sm;              // W*C = 16384 floats
    float* ct = sm + Ww*Cc;      // 256
    float* st = ct + 256;        // 256
    const int h = blockIdx.x, b = blockIdx.y;
    const int tid = threadIdx.x;
    const float* prow = pts + ((size_t)(b*Hh + h))*(Ww*Cc);
    for (int i = tid; i < (Ww*Cc)/4; i += 320)
        ((float4*)sP)[i] = ((const float4*)prow)[i];
    if (tid < 256) {
        float s, c;
        sincosf((float)tid * TWO_PI_OVER_256, &s, &c);
        ct[tid] = c; st[tid] = s;
    }
    __syncthreads();

    const int cg = tid & 15;     // c-group
    const int ky = tid >> 4;     // 0..19
    const int c0 = cg * 4;

    float ar0=0,ar1=0,ar2=0,ar3=0, ai0=0,ai1=0,ai2=0,ai3=0;
    int t = 0;
    #pragma unroll 4
    for (int w = 0; w < Ww; ++w) {
        float4 p = *(const float4*)(sP + w*Cc + c0);
        float cv = ct[t], sv = st[t];
        ar0 += p.x*cv; ai0 -= p.x*sv;
        ar1 += p.y*cv; ai1 -= p.y*sv;
        ar2 += p.z*cv; ai2 -= p.z*sv;
        ar3 += p.w*cv; ai3 -= p.w*sv;
        t = (t + ky) & 255;
    }
    float2* dst = g_A + (((size_t)(b*Hh + h))*M2m + ky)*Cc + c0;
    *(float4*)(dst + 0) = make_float4(ar0, ai0, ar1, ai1);
    *(float4*)(dst + 2) = make_float4(ar2, ai2, ar3, ai3);
}

// ---------------------------------------------------------------------------
// K2: M[b,ky,kx,c] = sum_h A[b,h,ky,c] * e^{-2*pi*i*(kx-10)*h/H}
// block = (ky, b); 256 threads = 4 kx-groups(5 each) * 64 c
// ---------------------------------------------------------------------------
#define HT 32
__global__ void __launch_bounds__(256) k_fwd_h() {
    __shared__ float2 sA[HT*Cc];
    __shared__ float ct[256], st[256];
    const int ky = blockIdx.x, b = blockIdx.y;
    const int tid = threadIdx.x;
    {
        float s, c;
        sincosf((float)tid * TWO_PI_OVER_256, &s, &c);
        ct[tid] = c; st[tid] = s;
    }
    const int cc = tid & 63, kg = tid >> 6;
    float ar[5] = {0,0,0,0,0}, ai[5] = {0,0,0,0,0};
    int f[5], t[5];
    #pragma unroll
    for (int j = 0; j < 5; ++j) { f[j] = (kg*5 + j + 246) & 255; t[j] = 0; }

    for (int h0 = 0; h0 < Hh; h0 += HT) {
        __syncthreads();
        for (int i = tid; i < HT*Cc; i += 256) {
            int hh = i >> 6, c = i & 63;
            sA[i] = g_A[(((size_t)(b*Hh + h0 + hh))*M2m + ky)*Cc + c];
        }
        __syncthreads();
        #pragma unroll 4
        for (int hh = 0; hh < HT; ++hh) {
            float2 a = sA[hh*Cc + cc];
            #pragma unroll
            for (int j = 0; j < 5; ++j) {
                float cv = ct[t[j]], sv = st[t[j]];
                ar[j] += a.x*cv + a.y*sv;
                ai[j] += a.y*cv - a.x*sv;
                t[j] = (t[j] + f[j]) & 255;
            }
        }
    }
    #pragma unroll
    for (int j = 0; j < 5; ++j) {
        int kx = kg*5 + j;
        g_M[(((size_t)(b*M2m + ky))*M1m + kx)*Cc + cc] = make_float2(ar[j], ai[j]);
    }
}

// ---------------------------------------------------------------------------
// K3: channel mix (complex 64x64 per mode) + fold alpha_ky/(H*W)
// block = kx*20+ky (400 blocks); 256 threads
// ---------------------------------------------------------------------------
__global__ void __launch_bounds__(256) k_mix(const float* __restrict__ kr,
                                             const float* __restrict__ ki) {
    __shared__ float sKr[64*65];
    __shared__ float sKi[64*65];
    __shared__ float2 sMin[16*64];
    const int kx = blockIdx.x / M2m, ky = blockIdx.x % M2m;
    const int tid = threadIdx.x;
    const size_t kbase = ((size_t)(kx*M2m + ky))*Cc*Cc;
    for (int idx = tid; idx < 64*64; idx += 256) {
        int i = idx >> 6, j = idx & 63;
        sKr[i*65 + j] = kr[kbase + idx];
        sKi[i*65 + j] = ki[kbase + idx];
    }
    for (int idx = tid; idx < 16*64; idx += 256) {
        int bb = idx >> 6, j = idx & 63;
        sMin[idx] = g_M[(((size_t)(bb*M2m + ky))*M1m + kx)*Cc + j];
    }
    __syncthreads();
    const float sc = (ky == 0 ? 1.0f : 2.0f) * (1.0f/65536.0f);
    const int i = tid & 63, bq = tid >> 6;
    float ar[4] = {0,0,0,0}, ai[4] = {0,0,0,0};
    for (int j = 0; j < 64; ++j) {
        float krv = sKr[i*65 + j], kiv = sKi[i*65 + j];
        #pragma unroll
        for (int r = 0; r < 4; ++r) {
            float2 m = sMin[(bq*4 + r)*64 + j];
            ar[r] += krv*m.x - kiv*m.y;
            ai[r] += krv*m.y + kiv*m.x;
        }
    }
    #pragma unroll
    for (int r = 0; r < 4; ++r) {
        int bb = bq*4 + r;
        g_Mo[(((size_t)(bb*M2m + ky))*M1m + kx)*Cc + i] =
            make_float2(ar[r]*sc, ai[r]*sc);
    }
}

// ---------------------------------------------------------------------------
// K4: T[b,h,ky,c] = sum_kx Mo[b,ky,kx,c] * e^{+2*pi*i*(kx-10)*h/H}
// block = (ky, b); 256 threads = 4 h-groups * 64 c
// ---------------------------------------------------------------------------
__global__ void __launch_bounds__(256) k_inv_h() {
    __shared__ float2 sMo[M1m*Cc];
    __shared__ float ct[256], st[256];
    const int ky = blockIdx.x, b = blockIdx.y;
    const int tid = threadIdx.x;
    {
        float s, c;
        sincosf((float)tid * TWO_PI_OVER_256, &s, &c);
        ct[tid] = c; st[tid] = s;
    }
    for (int i = tid; i < M1m*Cc; i += 256)
        sMo[i] = g_Mo[((size_t)(b*M2m + ky))*M1m*Cc + i];
    __syncthreads();
    const int cc = tid & 63, hg = tid >> 6;
    float mr[M1m], mi[M1m];
    #pragma unroll
    for (int kx = 0; kx < M1m; ++kx) {
        float2 m = sMo[kx*Cc + cc];
        mr[kx] = m.x; mi[kx] = m.y;
    }
    for (int h = hg; h < Hh; h += 4) {
        float ar = 0.f, ai = 0.f;
        #pragma unroll
        for (int kx = 0; kx < M1m; ++kx) {
            int tt = ((kx + 246)*h) & 255;
            float cv = ct[tt], sv = st[tt];
            ar += mr[kx]*cv - mi[kx]*sv;
            ai += mr[kx]*sv + mi[kx]*cv;
        }
        g_T[(((size_t)(b*Hh + h))*M2m + ky)*Cc + cc] = make_float2(ar, ai);
    }
}

// ---------------------------------------------------------------------------
// K5: out[b,h,w,c] = sum_ky (Tr*cos - Ti*sin) + sum_j P[w,j]*Wl[c,j] + P[w,c]
// block = (h, b); 256 threads as 16x16; each thread a 4w x 4c tile, 4 passes
// ---------------------------------------------------------------------------
__global__ void __launch_bounds__(256) k_final(const float* __restrict__ pts,
                                               const float* __restrict__ wl,
                                               float* __restrict__ out) {
    extern __shared__ float sm[];
    float* sP  = sm;                 // 16384  [w][c]
    float* sWt = sP + Ww*Cc;         // 4096   [j][c]  (transposed w_lin)
    float* sTr = sWt + Cc*Cc;        // 1280   [ky][c]
    float* sTi = sTr + M2m*Cc;       // 1280
    float* ct  = sTi + M2m*Cc;       // 256
    float* st  = ct + 256;           // 256
    const int h = blockIdx.x, b = blockIdx.y;
    const int tid = threadIdx.x;
    const size_t rowbase = ((size_t)(b*Hh + h))*(Ww*Cc);

    for (int i = tid; i < (Ww*Cc)/4; i += 256)
        ((float4*)sP)[i] = ((const float4*)(pts + rowbase))[i];
    for (int idx = tid; idx < Cc*Cc; idx += 256) {
        int c = idx >> 6, j = idx & 63;
        sWt[j*64 + c] = wl[idx];
    }
    {
        const float2* tsrc = g_T + ((size_t)(b*Hh + h))*M2m*Cc;
        for (int i = tid; i < M2m*Cc; i += 256) {
            float2 v = tsrc[i];
            sTr[i] = v.x; sTi[i] = v.y;
        }
    }
    {
        float s, c;
        sincosf((float)tid * TWO_PI_OVER_256, &s, &c);
        ct[tid] = c; st[tid] = s;
    }
    __syncthreads();

    const int tc = tid & 15, tw = tid >> 4;
    const int c0 = tc * 4;

    for (int pass = 0; pass < 4; ++pass) {
        const int w0 = pass*64 + tw*4;
        float acc[4][4];
        #pragma unroll
        for (int i = 0; i < 4; ++i)
            #pragma unroll
            for (int k = 0; k < 4; ++k) acc[i][k] = 0.f;

        // linear: acc[i][k] += P[w0+i][j] * Wl_t[j][c0+k]
        for (int j = 0; j < Cc; j += 4) {
            float4 P0 = *(const float4*)(sP + (w0+0)*Cc + j);
            float4 P1 = *(const float4*)(sP + (w0+1)*Cc + j);
            float4 P2 = *(const float4*)(sP + (w0+2)*Cc + j);
            float4 P3 = *(const float4*)(sP + (w0+3)*Cc + j);
            float4 B0 = *(const float4*)(sWt + (j+0)*Cc + c0);
            float4 B1 = *(const float4*)(sWt + (j+1)*Cc + c0);
            float4 B2 = *(const float4*)(sWt + (j+2)*Cc + c0);
            float4 B3 = *(const float4*)(sWt + (j+3)*Cc + c0);
#define LIN_ROW(iI, P)                                                        \
            acc[iI][0] += P.x*B0.x; acc[iI][0] += P.y*B1.x;                   \
            acc[iI][0] += P.z*B2.x; acc[iI][0] += P.w*B3.x;                   \
            acc[iI][1] += P.x*B0.y; acc[iI][1] += P.y*B1.y;                   \
            acc[iI][1] += P.z*B2.y; acc[iI][1] += P.w*B3.y;                   \
            acc[iI][2] += P.x*B0.z; acc[iI][2] += P.y*B1.z;                   \
            acc[iI][2] += P.z*B2.z; acc[iI][2] += P.w*B3.z;                   \
            acc[iI][3] += P.x*B0.w; acc[iI][3] += P.y*B1.w;                   \
            acc[iI][3] += P.z*B2.w; acc[iI][3] += P.w*B3.w;
            LIN_ROW(0, P0)
            LIN_ROW(1, P1)
            LIN_ROW(2, P2)
            LIN_ROW(3, P3)
#undef LIN_ROW
        }

        // spectral: acc[i][k] += Tr[ky][c0+k]*cos - Ti[ky][c0+k]*sin
        #pragma unroll 4
        for (int ky = 0; ky < M2m; ++ky) {
            float4 tr = *(const float4*)(sTr + ky*Cc + c0);
            float4 ti = *(const float4*)(sTi + ky*Cc + c0);
            #pragma unroll
            for (int i = 0; i < 4; ++i) {
                int tt = (ky*(w0+i)) & 255;
                float cv = ct[tt], sv = st[tt];
                acc[i][0] += tr.x*cv; acc[i][0] -= ti.x*sv;
                acc[i][1] += tr.y*cv; acc[i][1] -= ti.y*sv;
                acc[i][2] += tr.z*cv; acc[i][2] -= ti.z*sv;
                acc[i][3] += tr.w*cv; acc[i][3] -= ti.w*sv;
            }
        }

        // residual + store
        #pragma unroll
        for (int i = 0; i < 4; ++i) {
            float4 pv = *(const float4*)(sP + (w0+i)*Cc + c0);
            float4 o;
            o.x = acc[i][0] + pv.x;
            o.y = acc[i][1] + pv.y;
            o.z = acc[i][2] + pv.z;
            o.w = acc[i][3] + pv.w;
            *(float4*)(out + rowbase + (size_t)(w0+i)*Cc + c0) = o;
        }
    }
}

// ---------------------------------------------------------------------------
extern "C" void kernel_launch(void* const* d_in, const int* in_sizes, int n_in,
                              void* d_out, int out_size) {
    (void)in_sizes; (void)n_in; (void)out_size;
    const float* pts = (const float*)d_in[0];
    const float* kr  = (const float*)d_in[1];
    const float* ki  = (const float*)d_in[2];
    const float* wl  = (const float*)d_in[3];
    float* out = (float*)d_out;

    const int sm1 = (Ww*Cc + 512) * (int)sizeof(float);                       // ~66 KB
    const int sm5 = (Ww*Cc + Cc*Cc + 2*M2m*Cc + 512) * (int)sizeof(float);    // ~92 KB
    cudaFuncSetAttribute(k_fwd_w, cudaFuncAttributeMaxDynamicSharedMemorySize, sm1);
    cudaFuncSetAttribute(k_final, cudaFuncAttributeMaxDynamicSharedMemorySize, sm5);

    k_fwd_w<<<dim3(Hh, Bb), 320, sm1>>>(pts);
    k_fwd_h<<<dim3(M2m, Bb), 256>>>();
    k_mix  <<<M1m*M2m, 256>>>(kr, ki);
    k_inv_h<<<dim3(M2m, Bb), 256>>>();
    k_final<<<dim3(Hh, Bb), 256, sm5>>>(pts, wl, out);
}